// round 14
// baseline (speedup 1.0000x reference)
#include <cuda_runtime.h>
#include <cstdint>

#define NB   2
#define NPTS 8192
#define CIN  128
#define COUT 128
#define KNN  21
#define FULLM 0xffffffffu
#define SENT 0xFFFFFFFFFFFFFFFFull
#define FINF __int_as_float(0x7f800000)

// packed f32x2 ops (sm_103a)
#define FMA2(d, a, b, c) asm("fma.rn.f32x2 %0, %1, %2, %3;" : "=l"(d) : "l"(a), "l"(b), "l"(c))
#define PACK2(d, lo, hi) asm("mov.b64 %0, {%1, %2};" : "=l"(d) : "f"(lo), "f"(hi))
#define UNPK2(lo, hi, s) asm("mov.b64 {%0, %1}, %2;" : "=f"(lo), "=f"(hi) : "l"(s))

// ---------------- scratch (device globals; no allocation allowed) -------------
__device__ __align__(16) float g_Ageo [NB * NPTS * 128];
__device__ __align__(16) float g_Btgeo[NB * NPTS * 128];
__device__ __align__(16) float g_Afeat[NB * NPTS * 128];
__device__ __align__(16) float g_Btfeat[NB * NPTS * 128];
__device__ int   g_idx[NB * NPTS * KNN];
__device__ __align__(16) float g_scale[256];
__device__ __align__(16) float g_shift[256];
__device__ __align__(16) float2 g_wp[128 * 128];   // [c][o] = (w1-w2, w2)

// ------------- prep: BN constants + weight transpose -------------------------
__global__ void __launch_bounds__(256) prep_kernel(
        const float* __restrict__ W_feat,
        const float* __restrict__ gg, const float* __restrict__ bg,
        const float* __restrict__ mg, const float* __restrict__ vg,
        const float* __restrict__ gf, const float* __restrict__ bf,
        const float* __restrict__ mf, const float* __restrict__ vf) {
    int idx = blockIdx.x * 256 + threadIdx.x;      // 64 blocks -> 16384
    int o = idx >> 7;          // coalesced read along c
    int c = idx & 127;
    float w1 = W_feat[o * 256 + c];
    float w2 = W_feat[o * 256 + 128 + c];
    g_wp[c * 128 + o] = make_float2(w1 - w2, w2);

    if (blockIdx.x == 0) {
        int t = threadIdx.x;
        if (t < 128) {
            float inv = gg[t] * rsqrtf(vg[t] + 1e-5f);
            g_scale[t] = inv;
            g_shift[t] = bg[t] - mg[t] * inv;
        } else {
            int oc = t - 128;
            float inv = gf[oc] * rsqrtf(vf[oc] + 1e-5f);
            g_scale[t] = inv;
            g_shift[t] = bf[oc] - mf[oc] * inv;
        }
    }
}

// ---------------- fused knn + precompute ------------------------------------
// Role split by blockIdx.x: [0,256) precompute 32-point tiles; [256,768) knn.
// The two roles have no data dependency (knn reads xyz only; precompute reads
// f/g_wp/W_geo) and complementary profiles (knn issue-bound, precompute
// latency-bound), so co-residency overlaps them. Shared-memory union.
#define KNN_CHUNK 1024
#define QCAP 80
#define PRE_BLKS 256    // NPTS/32

__global__ void __launch_bounds__(256) fused_kernel(
        const float* __restrict__ xyz, const float* __restrict__ f,
        const float* __restrict__ W_geo) {
    // union: knn needs 16384 (sc) + 16*QCAP*8 = 10240 (sQ) = 26624 bytes
    //        precompute needs 16384 (sf) + uses sxyz separately
    __shared__ __align__(16) unsigned char smraw[16384 + 16 * QCAP * 8];
    __shared__ float sxyz[32][3];

    int b = blockIdx.y;

    if (blockIdx.x < PRE_BLKS) {
        // ================= precompute role =================
        float (*sf)[32] = (float(*)[32])smraw;
        int n0 = blockIdx.x * 32;
        int o  = threadIdx.x & 127;
        int nh = threadIdx.x >> 7;          // 0/1: points [nh*16, nh*16+16)

        for (int t = threadIdx.x; t < 128 * 32; t += 256) {
            int c = t >> 5, n = t & 31;
            sf[c][n] = f[((size_t)b * 128 + c) * NPTS + n0 + n];
        }
        if (threadIdx.x < 96) {
            int n = threadIdx.x / 3, d = threadIdx.x % 3;
            sxyz[n][d] = xyz[((size_t)b * NPTS + n0 + n) * 3 + d];
        }
        __syncthreads();

        // geo: Ageo = (W03-W36).p ; Btgeo = W36.p   (16 points per thread)
        {
            float w0 = W_geo[o * 6 + 0], w1 = W_geo[o * 6 + 1], w2 = W_geo[o * 6 + 2];
            float w3 = W_geo[o * 6 + 3], w4 = W_geo[o * 6 + 4], w5 = W_geo[o * 6 + 5];
            float wa = w0 - w3, wb = w1 - w4, wc = w2 - w5;
#pragma unroll 4
            for (int t = 0; t < 16; ++t) {
                int n = nh * 16 + t;
                float x = sxyz[n][0], y = sxyz[n][1], z = sxyz[n][2];
                size_t base = ((size_t)b * NPTS + n0 + n) * 128 + o;
                g_Ageo [base] = fmaf(wa, x, fmaf(wb, y, wc * z));
                g_Btgeo[base] = fmaf(w3, x, fmaf(w4, y, w5 * z));
            }
        }

        // feat GEMM: 8 packed A-pairs + 8 packed B-pairs (16 points)
        unsigned long long accA[8], accB[8];
#pragma unroll
        for (int k = 0; k < 8; ++k) { accA[k] = 0ull; accB[k] = 0ull; }

        const float2* __restrict__ wp = g_wp;
#pragma unroll 4
        for (int c = 0; c < 128; ++c) {
            float2 w = __ldg(&wp[c * 128 + o]);      // coalesced, L1-resident
            unsigned long long wm2, w22;
            PACK2(wm2, w.x, w.x);
            PACK2(w22, w.y, w.y);
            const ulonglong2* row = (const ulonglong2*)&sf[c][nh * 16];
#pragma unroll
            for (int p = 0; p < 4; ++p) {
                ulonglong2 v = row[p];
                FMA2(accA[p * 2 + 0], wm2, v.x, accA[p * 2 + 0]);
                FMA2(accB[p * 2 + 0], w22, v.x, accB[p * 2 + 0]);
                FMA2(accA[p * 2 + 1], wm2, v.y, accA[p * 2 + 1]);
                FMA2(accB[p * 2 + 1], w22, v.y, accB[p * 2 + 1]);
            }
        }
#pragma unroll
        for (int k = 0; k < 8; ++k) {
            float a0, a1, b0, b1;
            UNPK2(a0, a1, accA[k]);
            UNPK2(b0, b1, accB[k]);
            size_t base = ((size_t)b * NPTS + n0 + nh * 16 + 2 * k) * 128 + o;
            g_Afeat [base]       = a0;
            g_Afeat [base + 128] = a1;
            g_Btfeat[base]       = b0;
            g_Btfeat[base + 128] = b1;
        }
        return;
    }

    // ================= knn role =================
    // Pass 1: per-lane min distance (1 FMNMX/cand). tau = 21st smallest of
    // the 32 lane-minima (subset => tau >= true d21: valid gate).
    // Pass 2: collect all dist <= tau (ballot-append, index order), then
    // exact top-21 by packed (flipped-dist, idx) key == lax.top_k semantics.
    float4* sc = (float4*)smraw;
    unsigned long long (*sQ)[QCAP] =
        (unsigned long long (*)[QCAP])(smraw + 16384);

    int bx   = blockIdx.x - PRE_BLKS;
    int warp = threadIdx.x >> 5;
    int lane = threadIdx.x & 31;
    int q0   = bx * 16 + warp * 2;
    int q1   = q0 + 1;

    const float* base = xyz + (size_t)b * NPTS * 3;
    float qx0 = base[q0 * 3 + 0], qy0 = base[q0 * 3 + 1], qz0 = base[q0 * 3 + 2];
    float qx1 = base[q1 * 3 + 0], qy1 = base[q1 * 3 + 1], qz1 = base[q1 * 3 + 2];
    float qd0 = fmaf(qx0, qx0, fmaf(qy0, qy0, qz0 * qz0));
    float qd1 = fmaf(qx1, qx1, fmaf(qy1, qy1, qz1 * qz1));

    float m0 = FINF, m1 = FINF;   // per-lane minimum distance per query

    // -------- pass 1 --------
    for (int cb = 0; cb < NPTS; cb += KNN_CHUNK) {
        __syncthreads();
        for (int i = threadIdx.x; i < KNN_CHUNK; i += 256) {
            int j = cb + i;
            float x = base[j * 3 + 0];
            float y = base[j * 3 + 1];
            float z = base[j * 3 + 2];
            float d2 = fmaf(x, x, fmaf(y, y, z * z));
            sc[i] = make_float4(x, y, z, d2);
        }
        __syncthreads();

#pragma unroll 4
        for (int i = lane; i < KNN_CHUNK; i += 32) {
            float4 c = sc[i];
            float dot0  = fmaf(qx0, c.x, fmaf(qy0, c.y, qz0 * c.z));
            float dist0 = fmaf(-2.f, dot0, qd0 + c.w);   // reference formula
            float dot1  = fmaf(qx1, c.x, fmaf(qy1, c.y, qz1 * c.z));
            float dist1 = fmaf(-2.f, dot1, qd1 + c.w);
            m0 = fminf(m0, dist0);
            m1 = fminf(m1, dist1);
        }
    }

    // tau = 21st smallest of the 32 lane minima (consume-one per round)
    float tau0, tau1;
    {
        float u = m0, mv;
#pragma unroll 1
        for (int r = 0; r < KNN; ++r) {
            mv = u;
#pragma unroll
            for (int off = 16; off; off >>= 1)
                mv = fminf(mv, __shfl_xor_sync(FULLM, mv, off));
            unsigned msk = __ballot_sync(FULLM, u == mv);
            if (lane == __ffs(msk) - 1) u = FINF;
        }
        tau0 = mv;
        u = m1;
#pragma unroll 1
        for (int r = 0; r < KNN; ++r) {
            mv = u;
#pragma unroll
            for (int off = 16; off; off >>= 1)
                mv = fminf(mv, __shfl_xor_sync(FULLM, mv, off));
            unsigned msk = __ballot_sync(FULLM, u == mv);
            if (lane == __ffs(msk) - 1) u = FINF;
        }
        tau1 = mv;
    }

    // -------- pass 2: collect all dist <= tau, in index order --------
    unsigned cnt0 = 0, cnt1 = 0;
    unsigned long long* Q0 = sQ[warp * 2 + 0];
    unsigned long long* Q1 = sQ[warp * 2 + 1];

    for (int cb = 0; cb < NPTS; cb += KNN_CHUNK) {
        __syncthreads();
        for (int i = threadIdx.x; i < KNN_CHUNK; i += 256) {
            int j = cb + i;
            float x = base[j * 3 + 0];
            float y = base[j * 3 + 1];
            float z = base[j * 3 + 2];
            float d2 = fmaf(x, x, fmaf(y, y, z * z));
            sc[i] = make_float4(x, y, z, d2);
        }
        __syncthreads();

#pragma unroll 4
        for (int i = lane; i < KNN_CHUNK; i += 32) {
            float4 c = sc[i];
            float dot0  = fmaf(qx0, c.x, fmaf(qy0, c.y, qz0 * c.z));
            float dist0 = fmaf(-2.f, dot0, qd0 + c.w);
            float dot1  = fmaf(qx1, c.x, fmaf(qy1, c.y, qz1 * c.z));
            float dist1 = fmaf(-2.f, dot1, qd1 + c.w);
            bool h0 = (dist0 <= tau0);
            bool h1 = (dist1 <= tau1);
            // single combined ballot on the fast path
            if (__ballot_sync(FULLM, h0 | h1)) {
                unsigned mk0 = __ballot_sync(FULLM, h0);
                unsigned mk1 = __ballot_sync(FULLM, h1);
                if (h0) {
                    unsigned u = __float_as_uint(dist0);
                    u ^= ((unsigned)((int)u >> 31)) | 0x80000000u;
                    unsigned off = cnt0 + __popc(mk0 & ((1u << lane) - 1u));
                    if (off < QCAP)
                        Q0[off] = ((unsigned long long)u << 32) | (unsigned)(cb + i);
                }
                if (h1) {
                    unsigned u = __float_as_uint(dist1);
                    u ^= ((unsigned)((int)u >> 31)) | 0x80000000u;
                    unsigned off = cnt1 + __popc(mk1 & ((1u << lane) - 1u));
                    if (off < QCAP)
                        Q1[off] = ((unsigned long long)u << 32) | (unsigned)(cb + i);
                }
                cnt0 += __popc(mk0);
                cnt1 += __popc(mk1);
            }
        }
    }
    __syncwarp();

    // -------- final: exact top-21 of each queue by (dist, idx) key --------
#pragma unroll 1
    for (int qi = 0; qi < 2; ++qi) {
        unsigned long long* Q = qi ? Q1 : Q0;
        int n = (int)(qi ? cnt1 : cnt0);
        if (n > QCAP) n = QCAP;
        unsigned long long k0 = (lane      < n) ? Q[lane]      : SENT;
        unsigned long long k1 = (lane + 32 < n) ? Q[lane + 32] : SENT;
        unsigned long long k2 = (lane + 64 < n) ? Q[lane + 64] : SENT;
        int myidx = 0;
#pragma unroll 1
        for (int r = 0; r < KNN; ++r) {
            unsigned long long lo = (k0 < k1) ? k0 : k1;
            unsigned long long best = (lo < k2) ? lo : k2;
            int bsrc = lane;
#pragma unroll
            for (int off = 16; off; off >>= 1) {
                unsigned long long ov = __shfl_xor_sync(FULLM, best, off);
                int os = __shfl_xor_sync(FULLM, bsrc, off);
                if (ov < best || (ov == best && os < bsrc)) { best = ov; bsrc = os; }
            }
            if (lane == r) myidx = (int)(best & 0xffffffffu);
            if (lane == bsrc) {           // keys unique (distinct idx)
                if      (k0 == best) k0 = SENT;
                else if (k1 == best) k1 = SENT;
                else                 k2 = SENT;
            }
        }
        if (lane < KNN)
            g_idx[((size_t)b * NPTS + (qi ? q1 : q0)) * KNN + lane] = myidx;
    }
}

// ---------------- gather-max + epilogue --------------------------------------
__device__ __forceinline__ float4 fmax4(float4 a, float4 b) {
    return make_float4(fmaxf(a.x, b.x), fmaxf(a.y, b.y),
                       fmaxf(a.z, b.z), fmaxf(a.w, b.w));
}

__global__ void __launch_bounds__(256) gather_max_kernel(float* __restrict__ out) {
    __shared__ int   sidx[32][KNN];
    __shared__ float sout[256 * 33];

    int b    = blockIdx.y;
    int n0   = blockIdx.x * 32;
    int warp = threadIdx.x >> 5;
    int lane = threadIdx.x & 31;

    for (int t = threadIdx.x; t < 32 * KNN; t += 256)
        sidx[t / KNN][t % KNN] = g_idx[((size_t)b * NPTS + n0) * KNN + t];
    __syncthreads();

    const float4* BG = (const float4*)g_Btgeo;
    const float4* BF = (const float4*)g_Btfeat;
    const float4* AG = (const float4*)g_Ageo;
    const float4* AF = (const float4*)g_Afeat;
    const float4* S4 = (const float4*)g_scale;
    const float4* H4 = (const float4*)g_shift;

    float4 scg = S4[lane],        shg = H4[lane];
    float4 scf = S4[32 + lane],   shf = H4[32 + lane];

    for (int pi = 0; pi < 4; ++pi) {
        int p = warp * 4 + pi;
        int n = n0 + p;
        float4 mg = make_float4(-3.4e38f, -3.4e38f, -3.4e38f, -3.4e38f);
        float4 mf = mg;
#pragma unroll
        for (int k = 0; k < KNN; ++k) {
            int j = sidx[p][k];
            size_t col = ((size_t)b * NPTS + j) * 32 + lane;
            mg = fmax4(mg, BG[col]);
            mf = fmax4(mf, BF[col]);
        }
        size_t acol = ((size_t)b * NPTS + n) * 32 + lane;
        float4 ag = AG[acol];
        float4 af = AF[acol];

        int cg = lane * 4;
        sout[(cg + 0) * 33 + p] = fmaxf(fmaf(mg.x + ag.x, scg.x, shg.x), 0.f);
        sout[(cg + 1) * 33 + p] = fmaxf(fmaf(mg.y + ag.y, scg.y, shg.y), 0.f);
        sout[(cg + 2) * 33 + p] = fmaxf(fmaf(mg.z + ag.z, scg.z, shg.z), 0.f);
        sout[(cg + 3) * 33 + p] = fmaxf(fmaf(mg.w + ag.w, scg.w, shg.w), 0.f);
        int cf = 128 + lane * 4;
        sout[(cf + 0) * 33 + p] = fmaxf(fmaf(mf.x + af.x, scf.x, shf.x), 0.f);
        sout[(cf + 1) * 33 + p] = fmaxf(fmaf(mf.y + af.y, scf.y, shf.y), 0.f);
        sout[(cf + 2) * 33 + p] = fmaxf(fmaf(mf.z + af.z, scf.z, shf.z), 0.f);
        sout[(cf + 3) * 33 + p] = fmaxf(fmaf(mf.w + af.w, scf.w, shf.w), 0.f);
    }
    __syncthreads();

    for (int c = warp; c < 256; c += 8)
        out[((size_t)b * 256 + c) * NPTS + n0 + lane] = sout[c * 33 + lane];
}

// ---------------- launch ------------------------------------------------------
extern "C" void kernel_launch(void* const* d_in, const int* in_sizes, int n_in,
                              void* d_out, int out_size) {
    const float* xyz    = (const float*)d_in[0];
    const float* f      = (const float*)d_in[1];
    const float* W_geo  = (const float*)d_in[2];
    const float* g_geo  = (const float*)d_in[3];
    const float* b_geo  = (const float*)d_in[4];
    const float* m_geo  = (const float*)d_in[5];
    const float* v_geo  = (const float*)d_in[6];
    const float* W_feat = (const float*)d_in[7];
    const float* g_feat = (const float*)d_in[8];
    const float* b_feat = (const float*)d_in[9];
    const float* m_feat = (const float*)d_in[10];
    const float* v_feat = (const float*)d_in[11];
    float* out = (float*)d_out;

    prep_kernel<<<64, 256>>>(W_feat,
        g_geo, b_geo, m_geo, v_geo, g_feat, b_feat, m_feat, v_feat);
    fused_kernel<<<dim3(PRE_BLKS + NPTS / 16, NB), 256>>>(xyz, f, W_geo);
    gather_max_kernel<<<dim3(NPTS / 32, NB), 256>>>(out);
}

// round 15
// speedup vs baseline: 1.0868x; 1.0868x over previous
#include <cuda_runtime.h>
#include <cstdint>

#define NB   2
#define NPTS 8192
#define CIN  128
#define COUT 128
#define KNN  21
#define FULLM 0xffffffffu
#define SENT 0xFFFFFFFFFFFFFFFFull
#define FINF __int_as_float(0x7f800000)

// packed f32x2 ops (sm_103a)
#define FMA2(d, a, b, c) asm("fma.rn.f32x2 %0, %1, %2, %3;" : "=l"(d) : "l"(a), "l"(b), "l"(c))
#define PACK2(d, lo, hi) asm("mov.b64 %0, {%1, %2};" : "=l"(d) : "f"(lo), "f"(hi))
#define UNPK2(lo, hi, s) asm("mov.b64 {%0, %1}, %2;" : "=f"(lo), "=f"(hi) : "l"(s))

// ---------------- scratch (device globals; no allocation allowed) -------------
__device__ __align__(16) float g_Ageo [NB * NPTS * 128];
__device__ __align__(16) float g_Btgeo[NB * NPTS * 128];
__device__ __align__(16) float g_Afeat[NB * NPTS * 128];
__device__ __align__(16) float g_Btfeat[NB * NPTS * 128];
__device__ int   g_idx[NB * NPTS * KNN];
__device__ __align__(16) float g_scale[256];
__device__ __align__(16) float g_shift[256];
__device__ __align__(16) float2 g_wp[128 * 128];     // [c][o] = (w1-w2, w2)
__device__ __align__(16) float4 g_pts[NB * NPTS];    // (x, y, z, d2)

// ------------- prep: BN constants + weight transpose + packed points ---------
__global__ void __launch_bounds__(256) prep_kernel(
        const float* __restrict__ W_feat, const float* __restrict__ xyz,
        const float* __restrict__ gg, const float* __restrict__ bg,
        const float* __restrict__ mg, const float* __restrict__ vg,
        const float* __restrict__ gf, const float* __restrict__ bf,
        const float* __restrict__ mf, const float* __restrict__ vf) {
    int idx = blockIdx.x * 256 + threadIdx.x;      // 64 blocks -> 16384
    {   // weight transpose (coalesced read along c)
        int o = idx >> 7;
        int c = idx & 127;
        float w1 = W_feat[o * 256 + c];
        float w2 = W_feat[o * 256 + 128 + c];
        g_wp[c * 128 + o] = make_float2(w1 - w2, w2);
    }
    {   // packed points with precomputed squared norm (same fmaf chain as knn)
        float x = xyz[idx * 3 + 0];
        float y = xyz[idx * 3 + 1];
        float z = xyz[idx * 3 + 2];
        float d2 = fmaf(x, x, fmaf(y, y, z * z));
        g_pts[idx] = make_float4(x, y, z, d2);
    }
    if (blockIdx.x == 0) {
        int t = threadIdx.x;
        if (t < 128) {
            float inv = gg[t] * rsqrtf(vg[t] + 1e-5f);
            g_scale[t] = inv;
            g_shift[t] = bg[t] - mg[t] * inv;
        } else {
            int oc = t - 128;
            float inv = gf[oc] * rsqrtf(vf[oc] + 1e-5f);
            g_scale[t] = inv;
            g_shift[t] = bf[oc] - mf[oc] * inv;
        }
    }
}

// ------------- fused precompute: geo + feat GEMM (f32x2 point-pairs) ---------
// 32-point tile, 256 threads: thread = (o = tid&127, nh = tid>>7), 16 points.
// accA[k]/accB[k] hold packed point-pairs; weights dup-packed per channel.
__global__ void __launch_bounds__(256) precompute_kernel(
        const float* __restrict__ xyz, const float* __restrict__ f,
        const float* __restrict__ W_geo) {
    __shared__ __align__(16) float sf[128][32];
    __shared__ float sxyz[32][3];
    int b  = blockIdx.y;
    int n0 = blockIdx.x * 32;
    int o  = threadIdx.x & 127;
    int nh = threadIdx.x >> 7;          // 0/1: points [nh*16, nh*16+16)

    for (int t = threadIdx.x; t < 128 * 32; t += 256) {
        int c = t >> 5, n = t & 31;
        sf[c][n] = f[((size_t)b * 128 + c) * NPTS + n0 + n];
    }
    if (threadIdx.x < 96) {
        int n = threadIdx.x / 3, d = threadIdx.x % 3;
        sxyz[n][d] = xyz[((size_t)b * NPTS + n0 + n) * 3 + d];
    }
    __syncthreads();

    // geo: Ageo = (W03-W36).p ; Btgeo = W36.p   (16 points per thread)
    {
        float w0 = W_geo[o * 6 + 0], w1 = W_geo[o * 6 + 1], w2 = W_geo[o * 6 + 2];
        float w3 = W_geo[o * 6 + 3], w4 = W_geo[o * 6 + 4], w5 = W_geo[o * 6 + 5];
        float wa = w0 - w3, wb = w1 - w4, wc = w2 - w5;
#pragma unroll 4
        for (int t = 0; t < 16; ++t) {
            int n = nh * 16 + t;
            float x = sxyz[n][0], y = sxyz[n][1], z = sxyz[n][2];
            size_t base = ((size_t)b * NPTS + n0 + n) * 128 + o;
            g_Ageo [base] = fmaf(wa, x, fmaf(wb, y, wc * z));
            g_Btgeo[base] = fmaf(w3, x, fmaf(w4, y, w5 * z));
        }
    }

    // feat GEMM: 8 packed A-pairs + 8 packed B-pairs (16 points)
    unsigned long long accA[8], accB[8];
#pragma unroll
    for (int k = 0; k < 8; ++k) { accA[k] = 0ull; accB[k] = 0ull; }

    const float2* __restrict__ wp = g_wp;
#pragma unroll 4
    for (int c = 0; c < 128; ++c) {
        float2 w = __ldg(&wp[c * 128 + o]);          // coalesced, L1-resident
        unsigned long long wm2, w22;
        PACK2(wm2, w.x, w.x);
        PACK2(w22, w.y, w.y);
        const ulonglong2* row = (const ulonglong2*)&sf[c][nh * 16];
#pragma unroll
        for (int p = 0; p < 4; ++p) {
            ulonglong2 v = row[p];
            FMA2(accA[p * 2 + 0], wm2, v.x, accA[p * 2 + 0]);
            FMA2(accB[p * 2 + 0], w22, v.x, accB[p * 2 + 0]);
            FMA2(accA[p * 2 + 1], wm2, v.y, accA[p * 2 + 1]);
            FMA2(accB[p * 2 + 1], w22, v.y, accB[p * 2 + 1]);
        }
    }
#pragma unroll
    for (int k = 0; k < 8; ++k) {
        float a0, a1, b0, b1;
        UNPK2(a0, a1, accA[k]);
        UNPK2(b0, b1, accB[k]);
        size_t base = ((size_t)b * NPTS + n0 + nh * 16 + 2 * k) * 128 + o;
        g_Afeat [base]       = a0;
        g_Afeat [base + 128] = a1;
        g_Btfeat[base]       = b0;
        g_Btfeat[base + 128] = b1;
    }
}

// ---------------- KNN: two-pass, 2 queries/warp, per-lane top-1 bound --------
// Pass 1: each lane keeps only its single smallest distance (1 FMNMX/cand).
// tau = 21st smallest of the 32 lane-minima (subset of all candidates =>
// tau >= true d21, valid conservative gate). Expected pass-2 queue ~34.
// Pass 2: collect all dist <= tau (ballot-append, index order), then exact
// top-21 by packed (flipped-dist, idx) key == lax.top_k(-dist) semantics.
// Staging reads prepacked g_pts (x,y,z,d2) with one LDG.128 per 16B.
#define KNN_CHUNK 1024
#define QCAP 96

__global__ void __launch_bounds__(256) knn_kernel() {
    __shared__ float4 sc[KNN_CHUNK];
    __shared__ unsigned long long sQ[16][QCAP];

    int b    = blockIdx.y;
    int warp = threadIdx.x >> 5;
    int lane = threadIdx.x & 31;
    int q0   = blockIdx.x * 16 + warp * 2;
    int q1   = q0 + 1;

    const float4* __restrict__ pts = g_pts + (size_t)b * NPTS;
    float4 qp0 = __ldg(&pts[q0]);
    float4 qp1 = __ldg(&pts[q1]);
    float qx0 = qp0.x, qy0 = qp0.y, qz0 = qp0.z, qd0 = qp0.w;
    float qx1 = qp1.x, qy1 = qp1.y, qz1 = qp1.z, qd1 = qp1.w;

    float m0 = FINF, m1 = FINF;   // per-lane minimum distance per query

    // -------- pass 1 --------
    for (int cb = 0; cb < NPTS; cb += KNN_CHUNK) {
        __syncthreads();
        for (int i = threadIdx.x; i < KNN_CHUNK; i += 256)
            sc[i] = __ldg(&pts[cb + i]);
        __syncthreads();

#pragma unroll 4
        for (int i = lane; i < KNN_CHUNK; i += 32) {
            float4 c = sc[i];
            float dot0  = fmaf(qx0, c.x, fmaf(qy0, c.y, qz0 * c.z));
            float dist0 = fmaf(-2.f, dot0, qd0 + c.w);   // reference formula
            float dot1  = fmaf(qx1, c.x, fmaf(qy1, c.y, qz1 * c.z));
            float dist1 = fmaf(-2.f, dot1, qd1 + c.w);
            m0 = fminf(m0, dist0);
            m1 = fminf(m1, dist1);
        }
    }

    // tau = 21st smallest of the 32 lane minima (consume-one per round)
    float tau0, tau1;
    {
        float u = m0, mv;
#pragma unroll 1
        for (int r = 0; r < KNN; ++r) {
            mv = u;
#pragma unroll
            for (int off = 16; off; off >>= 1)
                mv = fminf(mv, __shfl_xor_sync(FULLM, mv, off));
            unsigned msk = __ballot_sync(FULLM, u == mv);
            if (lane == __ffs(msk) - 1) u = FINF;
        }
        tau0 = mv;
        u = m1;
#pragma unroll 1
        for (int r = 0; r < KNN; ++r) {
            mv = u;
#pragma unroll
            for (int off = 16; off; off >>= 1)
                mv = fminf(mv, __shfl_xor_sync(FULLM, mv, off));
            unsigned msk = __ballot_sync(FULLM, u == mv);
            if (lane == __ffs(msk) - 1) u = FINF;
        }
        tau1 = mv;
    }

    // -------- pass 2: collect all dist <= tau, in index order --------
    unsigned cnt0 = 0, cnt1 = 0;
    unsigned long long* Q0 = sQ[warp * 2 + 0];
    unsigned long long* Q1 = sQ[warp * 2 + 1];

    for (int cb = 0; cb < NPTS; cb += KNN_CHUNK) {
        __syncthreads();
        for (int i = threadIdx.x; i < KNN_CHUNK; i += 256)
            sc[i] = __ldg(&pts[cb + i]);
        __syncthreads();

#pragma unroll 4
        for (int i = lane; i < KNN_CHUNK; i += 32) {
            float4 c = sc[i];
            float dot0  = fmaf(qx0, c.x, fmaf(qy0, c.y, qz0 * c.z));
            float dist0 = fmaf(-2.f, dot0, qd0 + c.w);
            float dot1  = fmaf(qx1, c.x, fmaf(qy1, c.y, qz1 * c.z));
            float dist1 = fmaf(-2.f, dot1, qd1 + c.w);
            bool h0 = (dist0 <= tau0);
            bool h1 = (dist1 <= tau1);
            // single combined ballot on the fast path
            if (__ballot_sync(FULLM, h0 | h1)) {
                unsigned mk0 = __ballot_sync(FULLM, h0);
                unsigned mk1 = __ballot_sync(FULLM, h1);
                if (h0) {
                    unsigned u = __float_as_uint(dist0);
                    u ^= ((unsigned)((int)u >> 31)) | 0x80000000u;
                    unsigned off = cnt0 + __popc(mk0 & ((1u << lane) - 1u));
                    if (off < QCAP)
                        Q0[off] = ((unsigned long long)u << 32) | (unsigned)(cb + i);
                }
                if (h1) {
                    unsigned u = __float_as_uint(dist1);
                    u ^= ((unsigned)((int)u >> 31)) | 0x80000000u;
                    unsigned off = cnt1 + __popc(mk1 & ((1u << lane) - 1u));
                    if (off < QCAP)
                        Q1[off] = ((unsigned long long)u << 32) | (unsigned)(cb + i);
                }
                cnt0 += __popc(mk0);
                cnt1 += __popc(mk1);
            }
        }
    }
    __syncwarp();

    // -------- final: exact top-21 of each queue by (dist, idx) key --------
#pragma unroll 1
    for (int qi = 0; qi < 2; ++qi) {
        unsigned long long* Q = qi ? Q1 : Q0;
        int n = (int)(qi ? cnt1 : cnt0);
        if (n > QCAP) n = QCAP;
        unsigned long long k0 = (lane      < n) ? Q[lane]      : SENT;
        unsigned long long k1 = (lane + 32 < n) ? Q[lane + 32] : SENT;
        unsigned long long k2 = (lane + 64 < n) ? Q[lane + 64] : SENT;
        int myidx = 0;
#pragma unroll 1
        for (int r = 0; r < KNN; ++r) {
            unsigned long long lo = (k0 < k1) ? k0 : k1;
            unsigned long long best = (lo < k2) ? lo : k2;
            int bsrc = lane;
#pragma unroll
            for (int off = 16; off; off >>= 1) {
                unsigned long long ov = __shfl_xor_sync(FULLM, best, off);
                int os = __shfl_xor_sync(FULLM, bsrc, off);
                if (ov < best || (ov == best && os < bsrc)) { best = ov; bsrc = os; }
            }
            if (lane == r) myidx = (int)(best & 0xffffffffu);
            if (lane == bsrc) {           // keys unique (distinct idx)
                if      (k0 == best) k0 = SENT;
                else if (k1 == best) k1 = SENT;
                else                 k2 = SENT;
            }
        }
        if (lane < KNN)
            g_idx[((size_t)b * NPTS + (qi ? q1 : q0)) * KNN + lane] = myidx;
    }
}

// ---------------- gather-max + epilogue --------------------------------------
__device__ __forceinline__ float4 fmax4(float4 a, float4 b) {
    return make_float4(fmaxf(a.x, b.x), fmaxf(a.y, b.y),
                       fmaxf(a.z, b.z), fmaxf(a.w, b.w));
}

__global__ void __launch_bounds__(256) gather_max_kernel(float* __restrict__ out) {
    __shared__ int   sidx[32][KNN];
    __shared__ float sout[256 * 33];

    int b    = blockIdx.y;
    int n0   = blockIdx.x * 32;
    int warp = threadIdx.x >> 5;
    int lane = threadIdx.x & 31;

    for (int t = threadIdx.x; t < 32 * KNN; t += 256)
        sidx[t / KNN][t % KNN] = g_idx[((size_t)b * NPTS + n0) * KNN + t];
    __syncthreads();

    const float4* BG = (const float4*)g_Btgeo;
    const float4* BF = (const float4*)g_Btfeat;
    const float4* AG = (const float4*)g_Ageo;
    const float4* AF = (const float4*)g_Afeat;
    const float4* S4 = (const float4*)g_scale;
    const float4* H4 = (const float4*)g_shift;

    float4 scg = S4[lane],        shg = H4[lane];
    float4 scf = S4[32 + lane],   shf = H4[32 + lane];

    for (int pi = 0; pi < 4; ++pi) {
        int p = warp * 4 + pi;
        int n = n0 + p;
        float4 mg = make_float4(-3.4e38f, -3.4e38f, -3.4e38f, -3.4e38f);
        float4 mf = mg;
#pragma unroll
        for (int k = 0; k < KNN; ++k) {
            int j = sidx[p][k];
            size_t col = ((size_t)b * NPTS + j) * 32 + lane;
            mg = fmax4(mg, BG[col]);
            mf = fmax4(mf, BF[col]);
        }
        size_t acol = ((size_t)b * NPTS + n) * 32 + lane;
        float4 ag = AG[acol];
        float4 af = AF[acol];

        int cg = lane * 4;
        sout[(cg + 0) * 33 + p] = fmaxf(fmaf(mg.x + ag.x, scg.x, shg.x), 0.f);
        sout[(cg + 1) * 33 + p] = fmaxf(fmaf(mg.y + ag.y, scg.y, shg.y), 0.f);
        sout[(cg + 2) * 33 + p] = fmaxf(fmaf(mg.z + ag.z, scg.z, shg.z), 0.f);
        sout[(cg + 3) * 33 + p] = fmaxf(fmaf(mg.w + ag.w, scg.w, shg.w), 0.f);
        int cf = 128 + lane * 4;
        sout[(cf + 0) * 33 + p] = fmaxf(fmaf(mf.x + af.x, scf.x, shf.x), 0.f);
        sout[(cf + 1) * 33 + p] = fmaxf(fmaf(mf.y + af.y, scf.y, shf.y), 0.f);
        sout[(cf + 2) * 33 + p] = fmaxf(fmaf(mf.z + af.z, scf.z, shf.z), 0.f);
        sout[(cf + 3) * 33 + p] = fmaxf(fmaf(mf.w + af.w, scf.w, shf.w), 0.f);
    }
    __syncthreads();

    for (int c = warp; c < 256; c += 8)
        out[((size_t)b * 256 + c) * NPTS + n0 + lane] = sout[c * 33 + lane];
}

// ---------------- launch ------------------------------------------------------
extern "C" void kernel_launch(void* const* d_in, const int* in_sizes, int n_in,
                              void* d_out, int out_size) {
    const float* xyz    = (const float*)d_in[0];
    const float* f      = (const float*)d_in[1];
    const float* W_geo  = (const float*)d_in[2];
    const float* g_geo  = (const float*)d_in[3];
    const float* b_geo  = (const float*)d_in[4];
    const float* m_geo  = (const float*)d_in[5];
    const float* v_geo  = (const float*)d_in[6];
    const float* W_feat = (const float*)d_in[7];
    const float* g_feat = (const float*)d_in[8];
    const float* b_feat = (const float*)d_in[9];
    const float* m_feat = (const float*)d_in[10];
    const float* v_feat = (const float*)d_in[11];
    float* out = (float*)d_out;

    prep_kernel<<<64, 256>>>(W_feat, xyz,
        g_geo, b_geo, m_geo, v_geo, g_feat, b_feat, m_feat, v_feat);
    precompute_kernel<<<dim3(NPTS / 32, NB), 256>>>(xyz, f, W_geo);
    knn_kernel<<<dim3(NPTS / 16, NB), 256>>>();
    gather_max_kernel<<<dim3(NPTS / 32, NB), 256>>>(out);
}